// round 5
// baseline (speedup 1.0000x reference)
#include <cuda_runtime.h>
#include <math_constants.h>

// Problem constants
#define BB 16
#define NN 1024
#define MM 8192
#define MSPLIT 32
#define MCHUNK (MM / MSPLIT)      // 256 targets per block
#define NPAIR (MCHUNK / 2)        // 128 packed target pairs
#define TPB 256
#define PPT 4                     // binder points per thread
#define KSEL 204                  // int(0.2 * 1024)

typedef unsigned long long ull;

// Scratch — plain stores only (no init kernel needed). Counter self-resets.
__device__ float    g_part[MSPLIT][BB * NN];   // partial min d2 per split
__device__ float    g_rep [MSPLIT * BB];       // repel partial per (split,b)
__device__ unsigned g_cnt [BB];                // zero at load; reset each launch

// ---- f32x2 packed helpers (ptxas never auto-fuses these) ----
__device__ __forceinline__ ull fma2(ull a, ull b, ull c) {
    ull d; asm("fma.rn.f32x2 %0, %1, %2, %3;" : "=l"(d) : "l"(a), "l"(b), "l"(c));
    return d;
}
__device__ __forceinline__ ull add2(ull a, ull b) {
    ull d; asm("add.rn.f32x2 %0, %1, %2;" : "=l"(d) : "l"(a), "l"(b));
    return d;
}
__device__ __forceinline__ ull pack2(float lo, float hi) {
    ull p; asm("mov.b64 %0, {%1, %2};" : "=l"(p) : "f"(lo), "f"(hi));
    return p;
}
__device__ __forceinline__ float2 unpack2(ull p) {
    float2 f; asm("mov.b64 {%0, %1}, %2;" : "=f"(f.x), "=f"(f.y) : "l"(p));
    return f;
}

__global__ void __launch_bounds__(TPB) fused_kernel(
    const float* __restrict__ binder,   // [16,1024,3]
    const float* __restrict__ target,   // [8192,3]
    float* __restrict__ out)            // [16]
{
    __shared__ ulonglong2 s_xy[NPAIR];  // {x01, y01} packed target pairs
    __shared__ ulonglong2 s_zw[NPAIR];  // {z01, w01},  w = |t|^2 (x -> -2x etc.)
    __shared__ float      s_warp[TPB / 32];
    __shared__ unsigned   hist[256];
    __shared__ unsigned   sh_sel, sh_rank;
    __shared__ int        sh_last;
    __shared__ float      s_fred[8];
    __shared__ unsigned   s_ured[8];

    const int b     = blockIdx.x;
    const int split = blockIdx.y;
    const int tid   = threadIdx.x;
    const int lane  = tid & 31, wid = tid >> 5;
    const int mbase = split * MCHUNK;

    // Preprocess + pack one target pair per thread (tid < NPAIR).
    if (tid < NPAIR) {
        const float* t0 = target + (size_t)(mbase + 2 * tid) * 3;
        const float* t1 = t0 + 3;
        float x0 = t0[0], y0 = t0[1], z0 = t0[2];
        float x1 = t1[0], y1 = t1[1], z1 = t1[2];
        float w0 = fmaf(x0, x0, fmaf(y0, y0, z0 * z0));
        float w1 = fmaf(x1, x1, fmaf(y1, y1, z1 * z1));
        s_xy[tid] = make_ulonglong2(pack2(-2.f * x0, -2.f * x1),
                                    pack2(-2.f * y0, -2.f * y1));
        s_zw[tid] = make_ulonglong2(pack2(-2.f * z0, -2.f * z1),
                                    pack2(w0, w1));
    }

    // Per-thread register block of PPT binder points, broadcast-packed.
    ull px2[PPT], py2[PPT], pz2[PPT], cc2[PPT];
    #pragma unroll
    for (int k = 0; k < PPT; ++k) {
        int n = tid + TPB * k;
        const float* p = binder + (size_t)(b * NN + n) * 3;
        float x = p[0], y = p[1], z = p[2];
        float c = fmaf(x, x, fmaf(y, y, z * z));
        px2[k] = pack2(x, x); py2[k] = pack2(y, y); pz2[k] = pack2(z, z);
        cc2[k] = pack2(c, c);
    }
    __syncthreads();

    float m[PPT];
    #pragma unroll
    for (int k = 0; k < PPT; ++k) m[k] = CUDART_INF_F;
    float rep = 0.f;

    #pragma unroll 2
    for (int jp = 0; jp < NPAIR; ++jp) {
        ulonglong2 xy = s_xy[jp];       // LDS.128
        ulonglong2 zw = s_zw[jp];       // LDS.128

        float dlo[PPT], dhi[PPT];
        float vi = CUDART_INF_F;        // min d2 this iteration (exact)
        #pragma unroll
        for (int k = 0; k < PPT; ++k) {
            ull s01 = fma2(px2[k], xy.x, zw.y);    // px*x' + w
            s01 = fma2(py2[k], xy.y, s01);
            s01 = fma2(pz2[k], zw.x, s01);
            ull d01 = add2(cc2[k], s01);           // d2 pair
            float2 d = unpack2(d01);
            dlo[k] = d.x; dhi[k] = d.y;
            float dm = fminf(d.x, d.y);
            m[k] = fminf(m[k], dm);
            vi   = fminf(vi, dm);
        }

        // One rare, EXACT divergence point per iteration: any d2 < 9.
        if (__builtin_expect(vi < 9.f, 0)) {
            #pragma unroll
            for (int k = 0; k < PPT; ++k) {
                if (dlo[k] < 9.f) {
                    float cl = 3.f - sqrtf(fmaxf(dlo[k], 0.f));
                    rep = fmaf(cl, cl, rep);
                }
                if (dhi[k] < 9.f) {
                    float cl = 3.f - sqrtf(fmaxf(dhi[k], 0.f));
                    rep = fmaf(cl, cl, rep);
                }
            }
        }
    }

    // Plain partial stores (coalesced) — no atomics, no init required.
    #pragma unroll
    for (int k = 0; k < PPT; ++k) {
        int n = tid + TPB * k;
        g_part[split][b * NN + n] = fmaxf(m[k], 0.f);
    }

    // Block repel partial.
    #pragma unroll
    for (int off = 16; off; off >>= 1)
        rep += __shfl_xor_sync(0xffffffffu, rep, off);
    if (lane == 0) s_warp[wid] = rep;
    __syncthreads();
    if (tid == 0) {
        float r = 0.f;
        #pragma unroll
        for (int w = 0; w < TPB / 32; ++w) r += s_warp[w];
        g_rep[split * BB + b] = r;
    }

    // ---- Last-block-done election for this batch ----
    __threadfence();
    __syncthreads();
    if (tid == 0) {
        unsigned old = atomicAdd(&g_cnt[b], 1u);
        sh_last = (old == MSPLIT - 1);
        if (sh_last) g_cnt[b] = 0;      // self-reset: identical state every launch
    }
    __syncthreads();
    if (!sh_last) return;
    __threadfence();

    // ---- Finalize for batch b (one block) ----
    // 1. Min over splits (fixed order -> deterministic), keys in registers.
    unsigned keys[4];
    #pragma unroll
    for (int i = 0; i < 4; ++i) {
        int n = tid + 256 * i;
        float mn = CUDART_INF_F;
        #pragma unroll
        for (int s = 0; s < MSPLIT; ++s)
            mn = fminf(mn, g_part[s][b * NN + n]);
        keys[i] = __float_as_uint(mn);  // non-negative: bit order == value order
    }

    if (tid == 0) sh_rank = KSEL;
    __syncthreads();

    // 2. 4-pass MSB radix select for the KSEL-th smallest key.
    unsigned prefix = 0, prefmask = 0;
    #pragma unroll
    for (int pass = 0; pass < 4; ++pass) {
        const int shift = 24 - 8 * pass;
        hist[tid] = 0;
        __syncthreads();
        #pragma unroll
        for (int i = 0; i < 4; ++i)
            if ((keys[i] & prefmask) == prefix)
                atomicAdd(&hist[(keys[i] >> shift) & 255u], 1u);
        __syncthreads();
        if (tid < 32) {
            unsigned c8[8], tot = 0;
            #pragma unroll
            for (int i = 0; i < 8; ++i) { c8[i] = hist[tid * 8 + i]; tot += c8[i]; }
            unsigned incl = tot;
            #pragma unroll
            for (int off = 1; off < 32; off <<= 1) {
                unsigned x = __shfl_up_sync(0xffffffffu, incl, off);
                if (tid >= off) incl += x;
            }
            unsigned excl = incl - tot;
            unsigned r = sh_rank;
            __syncwarp();
            if (r > excl && r <= incl) {
                unsigned run = excl, sel = 0, nr = 0;
                #pragma unroll
                for (int i = 0; i < 8; ++i) {
                    if (run < r && r <= run + c8[i]) { sel = tid * 8 + i; nr = r - run; }
                    run += c8[i];
                }
                sh_sel  = sel;
                sh_rank = nr;
            }
        }
        __syncthreads();
        prefix   |= sh_sel << shift;
        prefmask |= 0xFFu   << shift;
    }
    const unsigned T = prefix;          // key of the KSEL-th smallest

    // 3. Sum sqrt(d2) below T, tie-correct, combine with repel.
    float ssum = 0.f; unsigned scnt = 0;
    #pragma unroll
    for (int i = 0; i < 4; ++i)
        if (keys[i] < T) { ssum += sqrtf(__uint_as_float(keys[i])); scnt++; }
    #pragma unroll
    for (int off = 16; off; off >>= 1) {
        ssum += __shfl_xor_sync(0xffffffffu, ssum, off);
        scnt += __shfl_xor_sync(0xffffffffu, scnt, off);
    }
    if (lane == 0) { s_fred[wid] = ssum; s_ured[wid] = scnt; }
    __syncthreads();

    if (tid < 32) {
        float rp = (tid < MSPLIT) ? g_rep[tid * BB + b] : 0.f;
        #pragma unroll
        for (int off = 16; off; off >>= 1)
            rp += __shfl_xor_sync(0xffffffffu, rp, off);
        if (tid == 0) {
            float st = 0.f; unsigned ct = 0;
            #pragma unroll
            for (int w = 0; w < 8; ++w) { st += s_fred[w]; ct += s_ured[w]; }
            float attract = (st + (float)(KSEL - ct) * sqrtf(__uint_as_float(T)))
                            * (1.f / (float)KSEL);
            out[b] = 10.f * attract + 5.f * rp;
        }
    }
}

extern "C" void kernel_launch(void* const* d_in, const int* in_sizes, int n_in,
                              void* d_out, int out_size)
{
    const float* binder = (const float*)d_in[0];   // 16*1024*3
    const float* target = (const float*)d_in[1];   // 8192*3
    float* out = (float*)d_out;                    // 16

    dim3 grid(BB, MSPLIT);                         // 16 x 32 = 512 blocks
    fused_kernel<<<grid, TPB>>>(binder, target, out);
}